// round 4
// baseline (speedup 1.0000x reference)
#include <cuda_runtime.h>
#include <cstdint>

#define BB 16
#define TT 64
#define CC 512
#define GPITCH 65   // padded row pitch (floats) for transposed g tile: kills 32-way STS conflicts

// Scratch (allocation-free rule: __device__ globals)
__device__ float g_VE[BB * TT * CC];   // x @ W_proj + b_proj
__device__ float g_XE[BB * TT * CC];   // x @ W_x    + b_x

// ---------------------------------------------------------------------------
// Kernel 1: both embedding GEMMs fused. 128 blocks x 8 rows, 512 threads.
// thread c owns output column c for 8 rows of both matrices.
// ---------------------------------------------------------------------------
__global__ __launch_bounds__(512) void embed_kernel(
    const float* __restrict__ x,
    const float* __restrict__ Wp, const float* __restrict__ bp,
    const float* __restrict__ Wx, const float* __restrict__ bx)
{
    __shared__ float xs[8 * CC];
    const int tid = threadIdx.x;
    const int r0  = blockIdx.x * 8;

    for (int idx = tid; idx < 8 * CC; idx += 512) xs[idx] = x[r0 * CC + idx];
    __syncthreads();

    const int c = tid;
    float accP[8], accX[8];
#pragma unroll
    for (int r = 0; r < 8; r++) { accP[r] = 0.f; accX[r] = 0.f; }

#pragma unroll 2
    for (int k = 0; k < CC; k++) {
        const float wp = Wp[k * CC + c];
        const float wx = Wx[k * CC + c];
#pragma unroll
        for (int r = 0; r < 8; r++) {
            const float xv = xs[r * CC + k];           // smem broadcast
            accP[r] = fmaf(xv, wp, accP[r]);
            accX[r] = fmaf(xv, wx, accX[r]);
        }
    }

    const float bpv = bp[c], bxv = bx[c];
#pragma unroll
    for (int r = 0; r < 8; r++) {
        g_VE[(r0 + r) * CC + c] = accP[r] + bpv;
        g_XE[(r0 + r) * CC + c] = accX[r] + bxv;
    }
}

// ---------------------------------------------------------------------------
// Kernel 2: one CTA per (b, i). Fused feature build + [64,512]x[512,512] GEMM
// (f32x2 packed FFMA) + sigmoid/mask + logsumexp + mean-over-C.
// ---------------------------------------------------------------------------
__global__ __launch_bounds__(512) void temporal_kernel(
    const float* __restrict__ x,
    const float* __restrict__ ts,
    const float* __restrict__ amask,
    const float* __restrict__ Wt,  const float* __restrict__ bt,
    const float* __restrict__ Wim, const float* __restrict__ bim,
    float* __restrict__ out)
{
    extern __shared__ float sm[];
    float* g     = sm;                    // [512][GPITCH] transposed relu(h); later reused as z[64][512]
    float* feat0 = sm + CC * GPITCH;      // 64
    float* feat1 = feat0 + TT;            // 64
    float* maskv = feat1 + TT;            // 64
    float* sout2 = maskv + TT;            // 64

    const int tid = threadIdx.x;
    const int b   = blockIdx.x >> 6;
    const int i   = blockIdx.x & 63;

    if (tid < TT) {
        const float ti  = ts[b * TT + i];
        const float tj  = ts[b * TT + tid];
        const float rel = ti - tj;
        feat0[tid] = log1pf(fmaxf(rel, 0.f));
        feat1[tid] = log1pf(fmaxf(-rel, 0.f));
        maskv[tid] = amask[b * TT + tid];
        sout2[tid] = 0.f;
    }
    __syncthreads();

    // ---- build g^T[k][j] = relu( f0[j]*Wt[0][k] + f1[j]*Wt[1][k] + bt[k] + XE[b][j][k] )
    {
        const int ck = tid;
        const float w0 = Wt[ck], w1 = Wt[CC + ck], b0 = bt[ck];
        const float* XEb = g_XE + b * TT * CC;
#pragma unroll 4
        for (int j = 0; j < TT; j++) {
            const float h = fmaf(feat0[j], w0, fmaf(feat1[j], w1, b0)) + XEb[j * CC + ck];
            g[ck * GPITCH + j] = fmaxf(h, 0.f);
        }
    }
    __syncthreads();

    // ---- GEMM: out[j][n] = sum_k g[j][k] * Wim[k][n], 8j x 8n per thread
    const int tc = tid & 63;      // n-group 0..63
    const int tjg = tid >> 6;     // j-group 0..7 (warp-uniform)
    const int j0 = tjg * 8;
    const int c0 = tc * 8;

    unsigned long long acc[8][4];
#pragma unroll
    for (int jj = 0; jj < 8; jj++)
#pragma unroll
        for (int cp = 0; cp < 4; cp++) acc[jj][cp] = 0ull;

    const float* Wbase = Wim + c0;
#pragma unroll 2
    for (int k = 0; k < CC; k++) {
        const ulonglong2* wrow = reinterpret_cast<const ulonglong2*>(Wbase + (size_t)k * CC);
        const ulonglong2 wA = wrow[0];   // (w[c0],w[c0+1]) , (w[c0+2],w[c0+3])
        const ulonglong2 wB = wrow[1];
        const float* grow = g + k * GPITCH + j0;
#pragma unroll
        for (int jj = 0; jj < 8; jj++) {
            const float gv = grow[jj];   // smem broadcast (all lanes same j-group? lanes share tjg)
            unsigned long long gp;
            asm("mov.b64 %0, {%1, %1};" : "=l"(gp) : "r"(__float_as_uint(gv)));
            asm("fma.rn.f32x2 %0, %1, %2, %0;" : "+l"(acc[jj][0]) : "l"(gp), "l"(wA.x));
            asm("fma.rn.f32x2 %0, %1, %2, %0;" : "+l"(acc[jj][1]) : "l"(gp), "l"(wA.y));
            asm("fma.rn.f32x2 %0, %1, %2, %0;" : "+l"(acc[jj][2]) : "l"(gp), "l"(wB.x));
            asm("fma.rn.f32x2 %0, %1, %2, %0;" : "+l"(acc[jj][3]) : "l"(gp), "l"(wB.y));
        }
    }
    __syncthreads();   // all g reads finished before we overwrite the region with z

    // ---- epilogue: p = sigmoid(s + b_imp)*mask; z = VE*p; psum for out2
    float bi[8];
#pragma unroll
    for (int cc = 0; cc < 8; cc++) bi[cc] = bim[c0 + cc];

    const float* VEb = g_VE + b * TT * CC;
    float* zbuf = sm;   // reuse as z[j][c], pitch CC (32768 floats < 33280)

    float psum[8];
#pragma unroll
    for (int jj = 0; jj < 8; jj++) {
        const int j = j0 + jj;
        const float mk = maskv[j];
        const float4 ve0 = *reinterpret_cast<const float4*>(VEb + j * CC + c0);
        const float4 ve1 = *reinterpret_cast<const float4*>(VEb + j * CC + c0 + 4);
        float zv[8];
        float ps = 0.f;
#pragma unroll
        for (int cp = 0; cp < 4; cp++) {
            unsigned int lo, hi;
            asm("mov.b64 {%0, %1}, %2;" : "=r"(lo), "=r"(hi) : "l"(acc[jj][cp]));
            const float s0 = __uint_as_float(lo) + bi[cp * 2];
            const float s1 = __uint_as_float(hi) + bi[cp * 2 + 1];
            const float p0 = mk / (1.f + __expf(-s0));
            const float p1 = mk / (1.f + __expf(-s1));
            ps += p0 + p1;
            zv[cp * 2]     = p0;
            zv[cp * 2 + 1] = p1;
        }
        zv[0] *= ve0.x; zv[1] *= ve0.y; zv[2] *= ve0.z; zv[3] *= ve0.w;
        zv[4] *= ve1.x; zv[5] *= ve1.y; zv[6] *= ve1.z; zv[7] *= ve1.w;

        float4* zp = reinterpret_cast<float4*>(zbuf + j * CC + c0);
        zp[0] = make_float4(zv[0], zv[1], zv[2], zv[3]);
        zp[1] = make_float4(zv[4], zv[5], zv[6], zv[7]);
        psum[jj] = ps;
    }

    // warp reduce psum (each warp is a single j-group); lane 0 accumulates
#pragma unroll
    for (int off = 16; off > 0; off >>= 1)
#pragma unroll
        for (int jj = 0; jj < 8; jj++)
            psum[jj] += __shfl_xor_sync(0xffffffffu, psum[jj], off);
    if ((tid & 31) == 0) {
#pragma unroll
        for (int jj = 0; jj < 8; jj++) atomicAdd(&sout2[j0 + jj], psum[jj]);
    }
    __syncthreads();

    // ---- per-column logsumexp over j (thread c = tid; fully coalesced smem reads)
    {
        const int c = tid;
        float m = -1e30f;
#pragma unroll 4
        for (int j = 0; j < TT; j++) m = fmaxf(m, zbuf[j * CC + c]);
        float ssum = 0.f;
#pragma unroll 4
        for (int j = 0; j < TT; j++) ssum += __expf(zbuf[j * CC + c] - m);
        const float lse = __logf(ssum) + m;
        const int row = b * TT + i;
        out[row * CC + c] = x[row * CC + c] + lse;
    }
    if (tid < TT) {
        out[BB * TT * CC + (b * TT + i) * TT + tid] = sout2[tid] * (1.f / 512.f);
    }
}

// ---------------------------------------------------------------------------
extern "C" void kernel_launch(void* const* d_in, const int* in_sizes, int n_in,
                              void* d_out, int out_size)
{
    const float* x     = (const float*)d_in[0];
    const float* ts    = (const float*)d_in[1];
    const float* amask = (const float*)d_in[2];
    const float* Wp    = (const float*)d_in[3];
    const float* bp    = (const float*)d_in[4];
    const float* Wx    = (const float*)d_in[5];
    const float* bx    = (const float*)d_in[6];
    const float* Wt    = (const float*)d_in[7];
    const float* bt    = (const float*)d_in[8];
    const float* Wim   = (const float*)d_in[9];
    const float* bim   = (const float*)d_in[10];
    float* out = (float*)d_out;

    embed_kernel<<<128, 512>>>(x, Wp, bp, Wx, bx);

    const size_t smem = (size_t)(CC * GPITCH + 4 * TT) * sizeof(float);  // 134144 B
    cudaFuncSetAttribute(temporal_kernel, cudaFuncAttributeMaxDynamicSharedMemorySize, (int)smem);
    temporal_kernel<<<BB * TT, 512, smem>>>(x, ts, amask, Wt, bt, Wim, bim, out);
}

// round 7
// speedup vs baseline: 2.2712x; 2.2712x over previous
#include <cuda_runtime.h>
#include <cuda_bf16.h>
#include <cstdint>

#define BB 16
#define TT 64
#define CC 512

// ---------------------------------------------------------------------------
// Device scratch (allocation-free rule)
// ---------------------------------------------------------------------------
__device__ float g_VE[BB * TT * CC];            // x @ W_proj + b_proj
__device__ float g_XE[BB * TT * CC];            // x @ W_x    + b_x
__device__ __nv_bfloat16 g_WimT[CC * CC];       // W_imp^T in bf16, [N][K]

// ---------------------------------------------------------------------------
// Helpers (baseline sm_80+ PTX only: mma.sync / ldmatrix / cp.async)
// ---------------------------------------------------------------------------
__device__ __forceinline__ uint32_t smem_u32(const void* p) {
    uint32_t a;
    asm("{ .reg .u64 t; cvta.to.shared.u64 t, %1; cvt.u32.u64 %0, t; }" : "=r"(a) : "l"(p));
    return a;
}
__device__ __forceinline__ void ldsm4(uint32_t* r, uint32_t addr) {
    asm volatile("ldmatrix.sync.aligned.m8n8.x4.shared.b16 {%0,%1,%2,%3}, [%4];"
        : "=r"(r[0]), "=r"(r[1]), "=r"(r[2]), "=r"(r[3]) : "r"(addr));
}
__device__ __forceinline__ void mma_bf16(float* d, const uint32_t* a, const uint32_t* b) {
    asm volatile("mma.sync.aligned.m16n8k16.row.col.f32.bf16.bf16.f32 "
        "{%0,%1,%2,%3}, {%4,%5,%6,%7}, {%8,%9}, {%0,%1,%2,%3};"
        : "+f"(d[0]), "+f"(d[1]), "+f"(d[2]), "+f"(d[3])
        : "r"(a[0]), "r"(a[1]), "r"(a[2]), "r"(a[3]), "r"(b[0]), "r"(b[1]));
}
__device__ __forceinline__ void cp_async16(uint32_t dst, const void* src) {
    asm volatile("cp.async.cg.shared.global [%0], [%1], 16;" :: "r"(dst), "l"(src));
}
#define CP_COMMIT() asm volatile("cp.async.commit_group;" ::: "memory")

// smem byte offsets
#define OFF_F0     0
#define OFF_F1     512
#define OFF_MASK   1024
#define OFF_SOUT2  1280
#define OFF_BIM    1792
#define OFF_WT0    3840
#define OFF_WT1    5888
#define OFF_BT     7936
#define OFF_A      10240        /* A: [128][512] bf16 swizzled = 131072 B */
#define OFF_B      141312       /* B: 2 x 16384 double buffer; aliased by z [128][130] f32 */
#define ZPITCH     130
#define SMEM_BYTES (141312 + 128 * ZPITCH * 4)   /* 207872 */

// ---------------------------------------------------------------------------
// Kernel: embedding GEMMs (x@W_proj+b, x@W_x+b)
// ---------------------------------------------------------------------------
__global__ __launch_bounds__(512) void embed_kernel(
    const float* __restrict__ x,
    const float* __restrict__ Wp, const float* __restrict__ bp,
    const float* __restrict__ Wx, const float* __restrict__ bx)
{
    __shared__ float xs[8 * CC];
    const int tid = threadIdx.x;
    const int r0  = blockIdx.x * 8;
    for (int idx = tid; idx < 8 * CC; idx += 512) xs[idx] = x[r0 * CC + idx];
    __syncthreads();
    const int c = tid;
    float accP[8], accX[8];
#pragma unroll
    for (int r = 0; r < 8; r++) { accP[r] = 0.f; accX[r] = 0.f; }
#pragma unroll 2
    for (int k = 0; k < CC; k++) {
        const float wp = Wp[k * CC + c];
        const float wx = Wx[k * CC + c];
#pragma unroll
        for (int r = 0; r < 8; r++) {
            const float xv = xs[r * CC + k];
            accP[r] = fmaf(xv, wp, accP[r]);
            accX[r] = fmaf(xv, wx, accX[r]);
        }
    }
    const float bpv = bp[c], bxv = bx[c];
#pragma unroll
    for (int r = 0; r < 8; r++) {
        g_VE[(r0 + r) * CC + c] = accP[r] + bpv;
        g_XE[(r0 + r) * CC + c] = accX[r] + bxv;
    }
}

// ---------------------------------------------------------------------------
// Kernel: W_imp -> transposed bf16 [N][K]
// ---------------------------------------------------------------------------
__global__ void prep_wim_kernel(const float* __restrict__ Wim)
{
    __shared__ float tile[32][33];
    const int n0 = blockIdx.x * 32, k0 = blockIdx.y * 32;
    tile[threadIdx.y][threadIdx.x] = Wim[(k0 + threadIdx.y) * CC + n0 + threadIdx.x];
    __syncthreads();
    g_WimT[(n0 + threadIdx.y) * CC + k0 + threadIdx.x] =
        __float2bfloat16(tile[threadIdx.x][threadIdx.y]);
}

// ---------------------------------------------------------------------------
// Main fused kernel: one CTA per (b, i-pair). M=128 (2 i x 64 j), K=512,
// N=512 in 4 chunks of 128. 256 threads = 8 warps, warp tile 32m x 64n,
// mma.sync m16n8k16 bf16 with fp32 accumulators.
// ---------------------------------------------------------------------------
__global__ __launch_bounds__(256, 1) void temporal_kernel(
    const float* __restrict__ x,
    const float* __restrict__ ts,
    const float* __restrict__ amask,
    const float* __restrict__ Wt,  const float* __restrict__ bt,
    const float* __restrict__ bim,
    float* __restrict__ out)
{
    extern __shared__ char sm[];
    const uint32_t smb = smem_u32(sm);
    const int tid  = threadIdx.x;
    const int lane = tid & 31;
    const int wid  = tid >> 5;

    const int b    = blockIdx.x >> 5;
    const int pair = blockIdx.x & 31;
    const int i0   = pair * 2;

    float* f0s   = (float*)(sm + OFF_F0);
    float* f1s   = (float*)(sm + OFF_F1);
    float* maskv = (float*)(sm + OFF_MASK);
    float* sout2 = (float*)(sm + OFF_SOUT2);
    float* sbim  = (float*)(sm + OFF_BIM);
    float* sWt0  = (float*)(sm + OFF_WT0);
    float* sWt1  = (float*)(sm + OFF_WT1);
    float* sbt   = (float*)(sm + OFF_BT);

    // ---- staging ----
    for (int idx = tid; idx < CC; idx += 256) {
        sbim[idx] = bim[idx];
        sWt0[idx] = Wt[idx];
        sWt1[idx] = Wt[CC + idx];
        sbt[idx]  = bt[idx];
    }
    if (tid < 128) {
        const int ih = tid >> 6, jj = tid & 63;
        const float rel = ts[b * TT + i0 + ih] - ts[b * TT + jj];
        f0s[tid] = log1pf(fmaxf(rel, 0.f));
        f1s[tid] = log1pf(fmaxf(-rel, 0.f));
        sout2[tid] = 0.f;
    }
    if (tid < 64) maskv[tid] = amask[b * TT + tid];
    __syncthreads();

    // ---- build A = relu(h) [128 m][512 k] bf16, XOR-swizzled 16B chunks ----
    {
        const int m     = tid >> 1;
        const int khalf = tid & 1;
        const float f0v = f0s[m], f1v = f1s[m];
        const int xr = m & 7;
        const float* XEr = g_XE + (size_t)(b * TT + (m & 63)) * CC + khalf * 256;
        char* Arow = sm + OFF_A + m * 1024;
#pragma unroll 4
        for (int kc = 0; kc < 32; kc++) {
            const int c8 = khalf * 32 + kc;
            const int kg = khalf * 256 + kc * 8;
            const float4 x0 = *(const float4*)(XEr + kc * 8);
            const float4 x1 = *(const float4*)(XEr + kc * 8 + 4);
            float h[8];
            h[0] = fmaxf(fmaf(f0v, sWt0[kg+0], fmaf(f1v, sWt1[kg+0], sbt[kg+0])) + x0.x, 0.f);
            h[1] = fmaxf(fmaf(f0v, sWt0[kg+1], fmaf(f1v, sWt1[kg+1], sbt[kg+1])) + x0.y, 0.f);
            h[2] = fmaxf(fmaf(f0v, sWt0[kg+2], fmaf(f1v, sWt1[kg+2], sbt[kg+2])) + x0.z, 0.f);
            h[3] = fmaxf(fmaf(f0v, sWt0[kg+3], fmaf(f1v, sWt1[kg+3], sbt[kg+3])) + x0.w, 0.f);
            h[4] = fmaxf(fmaf(f0v, sWt0[kg+4], fmaf(f1v, sWt1[kg+4], sbt[kg+4])) + x1.x, 0.f);
            h[5] = fmaxf(fmaf(f0v, sWt0[kg+5], fmaf(f1v, sWt1[kg+5], sbt[kg+5])) + x1.y, 0.f);
            h[6] = fmaxf(fmaf(f0v, sWt0[kg+6], fmaf(f1v, sWt1[kg+6], sbt[kg+6])) + x1.z, 0.f);
            h[7] = fmaxf(fmaf(f0v, sWt0[kg+7], fmaf(f1v, sWt1[kg+7], sbt[kg+7])) + x1.w, 0.f);
            uint4 pk;
            __nv_bfloat162* pp = (__nv_bfloat162*)&pk;
            pp[0] = __floats2bfloat162_rn(h[0], h[1]);
            pp[1] = __floats2bfloat162_rn(h[2], h[3]);
            pp[2] = __floats2bfloat162_rn(h[4], h[5]);
            pp[3] = __floats2bfloat162_rn(h[6], h[7]);
            *(uint4*)(Arow + ((c8 ^ xr) << 4)) = pk;
        }
    }
    __syncthreads();

    // ---- per-lane ldmatrix address precompute ----
    const int mw = wid & 3, nw = wid >> 2;
    const int m0  = mw * 32;
    const int n0w = nw * 64;
    const int mA  = m0 + (lane & 15);
    const int aC8 = lane >> 4;                            // 0/1 -> k-chunk +0/+1
    const int aXr = mA & 7;
    const uint32_t aBase = smb + OFF_A + mA * 1024;
    const int nB  = n0w + (lane & 7) + ((lane >> 4) << 3);
    const int bC8 = (lane >> 3) & 1;
    const int bXr = nB & 7;
    const uint32_t bRowOff = (uint32_t)nB * 128;

    const int qrow = lane >> 2, qcol = (lane & 3) * 2;
    float* zb = (float*)(sm + OFF_B);                     // z[128][ZPITCH], aliases B slots

#pragma unroll 1
    for (int ch = 0; ch < 4; ch++) {
        float acc[2][8][4];
#pragma unroll
        for (int mf = 0; mf < 2; mf++)
#pragma unroll
            for (int nf = 0; nf < 8; nf++)
#pragma unroll
                for (int d = 0; d < 4; d++) acc[mf][nf][d] = 0.f;

        // prologue: async-load B stage 0
        {
            const int n = tid >> 1, cq = (tid & 1) * 4;
            const uint32_t dstRow = smb + OFF_B + n * 128;
            const __nv_bfloat16* src = g_WimT + (size_t)(ch * 128 + n) * CC + cq * 8;
#pragma unroll
            for (int c = 0; c < 4; c++)
                cp_async16(dstRow + (((cq + c) ^ (n & 7)) << 4), src + c * 8);
            CP_COMMIT();
        }

#pragma unroll 1
        for (int s = 0; s < 8; s++) {
            const uint32_t Bslot = smb + OFF_B + (s & 1) * 16384;
            if (s < 7) {
                const int n = tid >> 1, cq = (tid & 1) * 4;
                const uint32_t dstRow = smb + OFF_B + ((s + 1) & 1) * 16384 + n * 128;
                const __nv_bfloat16* src = g_WimT + (size_t)(ch * 128 + n) * CC + (s + 1) * 64 + cq * 8;
#pragma unroll
                for (int c = 0; c < 4; c++)
                    cp_async16(dstRow + (((cq + c) ^ (n & 7)) << 4), src + c * 8);
                CP_COMMIT();
                asm volatile("cp.async.wait_group 1;" ::: "memory");
            } else {
                asm volatile("cp.async.wait_group 0;" ::: "memory");
            }
            __syncthreads();

#pragma unroll
            for (int ks4 = 0; ks4 < 4; ks4++) {
                uint32_t a0[4], a1[4], bf[4][4];
                const uint32_t swA = (uint32_t)(((s * 8 + ks4 * 2 + aC8) ^ aXr) << 4);
                ldsm4(a0, aBase + swA);
                ldsm4(a1, aBase + 16384 + swA);
                const uint32_t swB = (uint32_t)(((ks4 * 2 + bC8) ^ bXr) << 4);
                const uint32_t bA = Bslot + bRowOff + swB;
                ldsm4(bf[0], bA);
                ldsm4(bf[1], bA + 2048);
                ldsm4(bf[2], bA + 4096);
                ldsm4(bf[3], bA + 6144);
#pragma unroll
                for (int q = 0; q < 4; q++) {
                    mma_bf16(acc[0][q * 2],     a0, bf[q]);
                    mma_bf16(acc[0][q * 2 + 1], a0, bf[q] + 2);
                    mma_bf16(acc[1][q * 2],     a1, bf[q]);
                    mma_bf16(acc[1][q * 2 + 1], a1, bf[q] + 2);
                }
            }
            __syncthreads();
        }

        // ---- epilogue for this 128-column chunk ----
        float out2p[4];
#pragma unroll
        for (int mf = 0; mf < 2; mf++) {
#pragma unroll
            for (int h = 0; h < 2; h++) {
                const int r  = m0 + mf * 16 + qrow + h * 8;
                const float mk = maskv[r & 63];
                float ps = 0.f;
#pragma unroll
                for (int nf = 0; nf < 8; nf++) {
                    const int nl = n0w + nf * 8 + qcol;
                    const float s0 = acc[mf][nf][h * 2 + 0] + sbim[ch * 128 + nl];
                    const float s1 = acc[mf][nf][h * 2 + 1] + sbim[ch * 128 + nl + 1];
                    const float p0 = mk / (1.f + __expf(-s0));
                    const float p1 = mk / (1.f + __expf(-s1));
                    ps += p0 + p1;
                    *(float2*)(zb + r * ZPITCH + nl) = make_float2(p0, p1);
                }
                out2p[mf * 2 + h] = ps;
            }
        }
#pragma unroll
        for (int off = 1; off <= 2; off <<= 1)
#pragma unroll
            for (int q = 0; q < 4; q++)
                out2p[q] += __shfl_xor_sync(0xffffffffu, out2p[q], off);
        if ((lane & 3) == 0) {
#pragma unroll
            for (int mf = 0; mf < 2; mf++)
#pragma unroll
                for (int h = 0; h < 2; h++)
                    atomicAdd(&sout2[m0 + mf * 16 + qrow + h * 8], out2p[mf * 2 + h]);
        }
        __syncthreads();

        // per-column logsumexp over j, with VE multiply (coalesced gmem reads)
        {
            const int ih = tid >> 7;
            const int nl = tid & 127;
            const int ng = ch * 128 + nl;
            float* zc = zb + (ih * 64) * ZPITCH + nl;
            const float* VEc = g_VE + (size_t)(b * TT) * CC + ng;
            float mx = -1e30f;
#pragma unroll 4
            for (int j = 0; j < TT; j++) {
                const float z = VEc[j * CC] * zc[j * ZPITCH];
                zc[j * ZPITCH] = z;
                mx = fmaxf(mx, z);
            }
            float ss = 0.f;
#pragma unroll 4
            for (int j = 0; j < TT; j++) ss += __expf(zc[j * ZPITCH] - mx);
            const float lse = __logf(ss) + mx;
            const int row = b * TT + i0 + ih;
            out[(size_t)row * CC + ng] = x[(size_t)row * CC + ng] + lse;
        }
        __syncthreads();
    }

    // ---- out2: mean over C ----
    if (tid < 128) {
        const int ih = tid >> 6, j = tid & 63;
        out[BB * TT * CC + ((b * TT + i0 + ih) * TT + j)] = sout2[tid] * (1.f / 512.f);
    }
}

// ---------------------------------------------------------------------------
extern "C" void kernel_launch(void* const* d_in, const int* in_sizes, int n_in,
                              void* d_out, int out_size)
{
    const float* x     = (const float*)d_in[0];
    const float* ts    = (const float*)d_in[1];
    const float* amask = (const float*)d_in[2];
    const float* Wp    = (const float*)d_in[3];
    const float* bp    = (const float*)d_in[4];
    const float* Wx    = (const float*)d_in[5];
    const float* bx    = (const float*)d_in[6];
    const float* Wt    = (const float*)d_in[7];
    const float* bt    = (const float*)d_in[8];
    const float* Wim   = (const float*)d_in[9];
    const float* bim   = (const float*)d_in[10];
    float* out = (float*)d_out;

    prep_wim_kernel<<<dim3(16, 16), dim3(32, 32)>>>(Wim);
    embed_kernel<<<128, 512>>>(x, Wp, bp, Wx, bx);

    cudaFuncSetAttribute(temporal_kernel, cudaFuncAttributeMaxDynamicSharedMemorySize, SMEM_BYTES);
    temporal_kernel<<<BB * 32, 256, SMEM_BYTES>>>(x, ts, amask, Wt, bt, bim, out);
}

// round 8
// speedup vs baseline: 3.4361x; 1.5129x over previous
#include <cuda_runtime.h>
#include <cuda_bf16.h>
#include <cstdint>

#define BB 16
#define TT 64
#define CC 512

// ---------------------------------------------------------------------------
// Device scratch (allocation-free rule)
// ---------------------------------------------------------------------------
__device__ float g_VE[BB * TT * CC];            // x @ W_proj + b_proj
__device__ float g_XE[BB * TT * CC];            // x @ W_x    + b_x
__device__ __nv_bfloat16 g_WimT[CC * CC];       // W_imp^T in bf16, [N][K]

// ---------------------------------------------------------------------------
// Helpers (baseline sm_80+ PTX only: mma.sync / ldmatrix / cp.async)
// ---------------------------------------------------------------------------
__device__ __forceinline__ uint32_t smem_u32(const void* p) {
    uint32_t a;
    asm("{ .reg .u64 t; cvta.to.shared.u64 t, %1; cvt.u32.u64 %0, t; }" : "=r"(a) : "l"(p));
    return a;
}
__device__ __forceinline__ void ldsm4(uint32_t* r, uint32_t addr) {
    asm volatile("ldmatrix.sync.aligned.m8n8.x4.shared.b16 {%0,%1,%2,%3}, [%4];"
        : "=r"(r[0]), "=r"(r[1]), "=r"(r[2]), "=r"(r[3]) : "r"(addr));
}
__device__ __forceinline__ void mma_bf16(float* d, const uint32_t* a, const uint32_t* b) {
    asm volatile("mma.sync.aligned.m16n8k16.row.col.f32.bf16.bf16.f32 "
        "{%0,%1,%2,%3}, {%4,%5,%6,%7}, {%8,%9}, {%0,%1,%2,%3};"
        : "+f"(d[0]), "+f"(d[1]), "+f"(d[2]), "+f"(d[3])
        : "r"(a[0]), "r"(a[1]), "r"(a[2]), "r"(a[3]), "r"(b[0]), "r"(b[1]));
}
__device__ __forceinline__ void cp_async16(uint32_t dst, const void* src) {
    asm volatile("cp.async.cg.shared.global [%0], [%1], 16;" :: "r"(dst), "l"(src));
}
#define CP_COMMIT() asm volatile("cp.async.commit_group;" ::: "memory")

// smem byte offsets
#define OFF_F0     0
#define OFF_F1     512
#define OFF_MASK   1024
#define OFF_SOUT2  1280
#define OFF_SEXP   1792
#define OFF_BIM    2816
#define OFF_WT0    4864
#define OFF_WT1    6912
#define OFF_BT     8960
#define OFF_A      11264        /* A: [128][512] bf16 swizzled = 131072 B */
#define OFF_B      142336       /* B: 2 x 16384 double buffer            */
#define SMEM_BYTES 175104

// ---------------------------------------------------------------------------
// Kernel: embedding GEMMs (x@W_proj+b, x@W_x+b)
// ---------------------------------------------------------------------------
__global__ __launch_bounds__(512) void embed_kernel(
    const float* __restrict__ x,
    const float* __restrict__ Wp, const float* __restrict__ bp,
    const float* __restrict__ Wx, const float* __restrict__ bx)
{
    __shared__ float xs[8 * CC];
    const int tid = threadIdx.x;
    const int r0  = blockIdx.x * 8;
    for (int idx = tid; idx < 8 * CC; idx += 512) xs[idx] = x[r0 * CC + idx];
    __syncthreads();
    const int c = tid;
    float accP[8], accX[8];
#pragma unroll
    for (int r = 0; r < 8; r++) { accP[r] = 0.f; accX[r] = 0.f; }
#pragma unroll 2
    for (int k = 0; k < CC; k++) {
        const float wp = Wp[k * CC + c];
        const float wx = Wx[k * CC + c];
#pragma unroll
        for (int r = 0; r < 8; r++) {
            const float xv = xs[r * CC + k];
            accP[r] = fmaf(xv, wp, accP[r]);
            accX[r] = fmaf(xv, wx, accX[r]);
        }
    }
    const float bpv = bp[c], bxv = bx[c];
#pragma unroll
    for (int r = 0; r < 8; r++) {
        g_VE[(r0 + r) * CC + c] = accP[r] + bpv;
        g_XE[(r0 + r) * CC + c] = accX[r] + bxv;
    }
}

// ---------------------------------------------------------------------------
// Kernel: W_imp -> transposed bf16 [N][K]
// ---------------------------------------------------------------------------
__global__ void prep_wim_kernel(const float* __restrict__ Wim)
{
    __shared__ float tile[32][33];
    const int n0 = blockIdx.x * 32, k0 = blockIdx.y * 32;
    tile[threadIdx.y][threadIdx.x] = Wim[(k0 + threadIdx.y) * CC + n0 + threadIdx.x];
    __syncthreads();
    g_WimT[(n0 + threadIdx.y) * CC + k0 + threadIdx.x] =
        __float2bfloat16(tile[threadIdx.x][threadIdx.y]);
}

// ---------------------------------------------------------------------------
// Main fused kernel: one CTA per (b, i-pair). M=128 (2 i x 64 j), K=512,
// N=512 in 4 chunks of 128. 512 threads = 16 warps (4 mw x 4 nw),
// warp tile 32m x 32n, mma.sync m16n8k16 bf16, register-resident epilogue.
// ---------------------------------------------------------------------------
__global__ __launch_bounds__(512, 1) void temporal_kernel(
    const float* __restrict__ x,
    const float* __restrict__ ts,
    const float* __restrict__ amask,
    const float* __restrict__ Wt,  const float* __restrict__ bt,
    const float* __restrict__ bim,
    float* __restrict__ out)
{
    extern __shared__ char sm[];
    const uint32_t smb = smem_u32(sm);
    const int tid  = threadIdx.x;
    const int lane = tid & 31;
    const int wid  = tid >> 5;

    const int b    = blockIdx.x >> 5;
    const int pair = blockIdx.x & 31;
    const int i0   = pair * 2;

    float* f0s   = (float*)(sm + OFF_F0);     // [128]
    float* f1s   = (float*)(sm + OFF_F1);
    float* maskv = (float*)(sm + OFF_MASK);   // [64]
    float* sout2 = (float*)(sm + OFF_SOUT2);  // [128]
    float* sexp  = (float*)(sm + OFF_SEXP);   // [2][128] per-chunk column exp-sums
    float* sbim  = (float*)(sm + OFF_BIM);    // [512]
    float* sWt0  = (float*)(sm + OFF_WT0);
    float* sWt1  = (float*)(sm + OFF_WT1);
    float* sbt   = (float*)(sm + OFF_BT);

    // ---- staging ----
    sbim[tid] = bim[tid];
    sWt0[tid] = Wt[tid];
    sWt1[tid] = Wt[CC + tid];
    sbt[tid]  = bt[tid];
    if (tid < 128) {
        const int ih = tid >> 6, jj = tid & 63;
        const float rel = ts[b * TT + i0 + ih] - ts[b * TT + jj];
        f0s[tid] = log1pf(fmaxf(rel, 0.f));
        f1s[tid] = log1pf(fmaxf(-rel, 0.f));
        sout2[tid] = 0.f;
    }
    if (tid < 64) maskv[tid] = amask[b * TT + tid];
    if (tid < 256) sexp[tid] = 0.f;
    __syncthreads();

    // ---- build A = relu(h) [128 m][512 k] bf16, XOR-swizzled 16B chunks ----
    // warp w owns rows [w*8, w*8+8); lanes sweep k contiguously (coalesced).
    {
        const int rbase = wid * 8;
#pragma unroll
        for (int rr = 0; rr < 8; rr++) {
            const int r = rbase + rr;
            const float f0v = f0s[r], f1v = f1s[r];
            const float* XEr = g_XE + (size_t)(b * TT + (r & 63)) * CC;
            char* Arow = sm + OFF_A + r * 1024;
            const int xr = r & 7;
#pragma unroll
            for (int pass = 0; pass < 4; pass++) {
                const int k = pass * 128 + lane * 4;
                const float4 xe = *(const float4*)(XEr + k);
                const float4 w0 = *(const float4*)(sWt0 + k);
                const float4 w1 = *(const float4*)(sWt1 + k);
                const float4 bb = *(const float4*)(sbt + k);
                const float h0 = fmaxf(fmaf(f0v, w0.x, fmaf(f1v, w1.x, bb.x)) + xe.x, 0.f);
                const float h1 = fmaxf(fmaf(f0v, w0.y, fmaf(f1v, w1.y, bb.y)) + xe.y, 0.f);
                const float h2 = fmaxf(fmaf(f0v, w0.z, fmaf(f1v, w1.z, bb.z)) + xe.z, 0.f);
                const float h3 = fmaxf(fmaf(f0v, w0.w, fmaf(f1v, w1.w, bb.w)) + xe.w, 0.f);
                uint2 pk;
                ((__nv_bfloat162*)&pk)[0] = __floats2bfloat162_rn(h0, h1);
                ((__nv_bfloat162*)&pk)[1] = __floats2bfloat162_rn(h2, h3);
                const int c8 = pass * 16 + (lane >> 1);
                *(uint2*)(Arow + ((c8 ^ xr) << 4) + ((lane & 1) << 3)) = pk;
            }
        }
    }
    __syncthreads();

    // ---- warp/lane geometry ----
    const int mw = wid & 3, nw = wid >> 2;
    const int m0  = mw * 32;
    const int n0w = nw * 32;
    const int mA  = m0 + (lane & 15);
    const int aC8 = lane >> 4;
    const int aXr = mA & 7;
    const uint32_t aBase = smb + OFF_A + mA * 1024;
    const int nB  = n0w + (lane & 7) + ((lane >> 4) << 3);
    const int bC8 = (lane >> 3) & 1;
    const int bXr = nB & 7;
    const uint32_t bRowOff = (uint32_t)nB * 128;
    const int qrow = lane >> 2, qcol2 = (lane & 3) * 2;

    // ---- B stage loader: stage = [128 n][64 k] bf16, 16 KB, XOR-swizzled ----
    auto issueB = [&](int ch, int s) {
        const int n  = tid >> 2;
        const int cq = (tid & 3) * 2;
        const uint32_t dstRow = smb + OFF_B + (s & 1) * 16384 + n * 128;
        const __nv_bfloat16* src = g_WimT + (size_t)(ch * 128 + n) * CC + s * 64 + cq * 8;
        cp_async16(dstRow + (((cq    ) ^ (n & 7)) << 4), src);
        cp_async16(dstRow + (((cq + 1) ^ (n & 7)) << 4), src + 8);
        CP_COMMIT();
    };
    issueB(0, 0);

#pragma unroll 1
    for (int ch = 0; ch < 4; ch++) {
        float acc[2][4][4];
#pragma unroll
        for (int mf = 0; mf < 2; mf++)
#pragma unroll
            for (int nf = 0; nf < 4; nf++)
#pragma unroll
                for (int d = 0; d < 4; d++) acc[mf][nf][d] = 0.f;

#pragma unroll 1
        for (int s = 0; s < 8; s++) {
            if (s < 7) {
                issueB(ch, s + 1);
                asm volatile("cp.async.wait_group 1;" ::: "memory");
            } else {
                asm volatile("cp.async.wait_group 0;" ::: "memory");
            }
            __syncthreads();
            const uint32_t Bslot = smb + OFF_B + (s & 1) * 16384;
#pragma unroll
            for (int t = 0; t < 4; t++) {
                uint32_t a0[4], a1[4], b0[4], b1[4];
                const uint32_t swA = (uint32_t)(((s * 8 + t * 2 + aC8) ^ aXr) << 4);
                ldsm4(a0, aBase + swA);
                ldsm4(a1, aBase + 16384 + swA);
                const uint32_t swB = (uint32_t)(((t * 2 + bC8) ^ bXr) << 4);
                const uint32_t bA = Bslot + bRowOff + swB;
                ldsm4(b0, bA);
                ldsm4(b1, bA + 2048);
                mma_bf16(acc[0][0], a0, b0);
                mma_bf16(acc[0][1], a0, b0 + 2);
                mma_bf16(acc[0][2], a0, b1);
                mma_bf16(acc[0][3], a0, b1 + 2);
                mma_bf16(acc[1][0], a1, b0);
                mma_bf16(acc[1][1], a1, b0 + 2);
                mma_bf16(acc[1][2], a1, b1);
                mma_bf16(acc[1][3], a1, b1 + 2);
            }
            __syncthreads();
        }

        // prefetch next chunk's first B stage; overlaps the epilogue below
        if (ch < 3) issueB(ch + 1, 0);

        // ---- register epilogue: sigmoid/mask, row sums (out2), column
        //      exp-sums (logsumexp) via shuffles + smem atomics ----
        float bimv[8];
#pragma unroll
        for (int nf = 0; nf < 4; nf++) {
            bimv[nf * 2]     = sbim[ch * 128 + n0w + nf * 8 + qcol2];
            bimv[nf * 2 + 1] = sbim[ch * 128 + n0w + nf * 8 + qcol2 + 1];
        }
        float cs[8];
#pragma unroll
        for (int c = 0; c < 8; c++) cs[c] = 0.f;
        float rs[4];
#pragma unroll
        for (int mf = 0; mf < 2; mf++) {
#pragma unroll
            for (int h = 0; h < 2; h++) {
                const int r  = m0 + mf * 16 + h * 8 + qrow;
                const float mk = maskv[r & 63];
                const float* VEr = g_VE + (size_t)(b * TT + (r & 63)) * CC
                                   + ch * 128 + n0w + qcol2;
                float rsum = 0.f;
#pragma unroll
                for (int nf = 0; nf < 4; nf++) {
                    const float2 ve = *(const float2*)(VEr + nf * 8);
                    const float s0 = acc[mf][nf][h * 2 + 0] + bimv[nf * 2];
                    const float s1 = acc[mf][nf][h * 2 + 1] + bimv[nf * 2 + 1];
                    const float p0 = mk / (1.f + __expf(-s0));
                    const float p1 = mk / (1.f + __expf(-s1));
                    rsum += p0 + p1;
                    cs[nf * 2]     += __expf(ve.x * p0);
                    cs[nf * 2 + 1] += __expf(ve.y * p1);
                }
                rs[mf * 2 + h] = rsum;
            }
        }
        // row sums -> sout2 (reduce over the 4 qcol lanes)
#pragma unroll
        for (int q = 0; q < 4; q++) {
            rs[q] += __shfl_xor_sync(0xffffffffu, rs[q], 1);
            rs[q] += __shfl_xor_sync(0xffffffffu, rs[q], 2);
        }
        if ((lane & 3) == 0) {
#pragma unroll
            for (int q = 0; q < 4; q++)
                atomicAdd(&sout2[m0 + (q >> 1) * 16 + (q & 1) * 8 + qrow], rs[q]);
        }
        // column exp-sums -> sexp (reduce over the 8 qrow lanes)
#pragma unroll
        for (int c = 0; c < 8; c++) {
            cs[c] += __shfl_xor_sync(0xffffffffu, cs[c], 4);
            cs[c] += __shfl_xor_sync(0xffffffffu, cs[c], 8);
            cs[c] += __shfl_xor_sync(0xffffffffu, cs[c], 16);
        }
        if (lane < 4) {
            const int ihl = mw >> 1;
#pragma unroll
            for (int nf = 0; nf < 4; nf++) {
                atomicAdd(&sexp[ihl * 128 + n0w + nf * 8 + lane * 2],     cs[nf * 2]);
                atomicAdd(&sexp[ihl * 128 + n0w + nf * 8 + lane * 2 + 1], cs[nf * 2 + 1]);
            }
        }
        __syncthreads();

        // out1 = x + log(sum_j exp(z)) for this chunk's 2x128 columns
        if (tid < 256) {
            const int ih = tid >> 7, cl = tid & 127;
            const int ng = ch * 128 + cl;
            const int row = b * TT + i0 + ih;
            out[(size_t)row * CC + ng] = x[(size_t)row * CC + ng] + __logf(sexp[tid]);
            sexp[tid] = 0.f;
        }
    }

    // ---- out2: mean over C ----
    __syncthreads();
    if (tid < 128) {
        const int ih = tid >> 6, j = tid & 63;
        out[BB * TT * CC + ((b * TT + i0 + ih) * TT + j)] = sout2[tid] * (1.f / 512.f);
    }
}

// ---------------------------------------------------------------------------
extern "C" void kernel_launch(void* const* d_in, const int* in_sizes, int n_in,
                              void* d_out, int out_size)
{
    const float* x     = (const float*)d_in[0];
    const float* ts    = (const float*)d_in[1];
    const float* amask = (const float*)d_in[2];
    const float* Wp    = (const float*)d_in[3];
    const float* bp    = (const float*)d_in[4];
    const float* Wx    = (const float*)d_in[5];
    const float* bx    = (const float*)d_in[6];
    const float* Wt    = (const float*)d_in[7];
    const float* bt    = (const float*)d_in[8];
    const float* Wim   = (const float*)d_in[9];
    const float* bim   = (const float*)d_in[10];
    float* out = (float*)d_out;

    prep_wim_kernel<<<dim3(16, 16), dim3(32, 32)>>>(Wim);
    embed_kernel<<<128, 512>>>(x, Wp, bp, Wx, bx);

    cudaFuncSetAttribute(temporal_kernel, cudaFuncAttributeMaxDynamicSharedMemorySize, SMEM_BYTES);
    temporal_kernel<<<BB * 32, 512, SMEM_BYTES>>>(x, ts, amask, Wt, bt, bim, out);
}

// round 9
// speedup vs baseline: 4.1161x; 1.1979x over previous
#include <cuda_runtime.h>
#include <cuda_bf16.h>
#include <cstdint>

#define BB 16
#define TT 64
#define CC 512

// ---------------------------------------------------------------------------
// Device scratch (allocation-free rule)
// ---------------------------------------------------------------------------
__device__ float g_VE[BB * TT * CC];            // x @ W_proj + b_proj
__device__ float g_XE[BB * TT * CC];            // x @ W_x    + b_x
__device__ __nv_bfloat16 g_WimT[CC * CC];       // W_imp^T in bf16, [N][K]

// ---------------------------------------------------------------------------
// Helpers (baseline sm_80+ PTX: mma.sync / ldmatrix / cp.async; f32x2 = sm_100+)
// ---------------------------------------------------------------------------
__device__ __forceinline__ uint32_t smem_u32(const void* p) {
    uint32_t a;
    asm("{ .reg .u64 t; cvta.to.shared.u64 t, %1; cvt.u32.u64 %0, t; }" : "=r"(a) : "l"(p));
    return a;
}
__device__ __forceinline__ void ldsm4(uint32_t* r, uint32_t addr) {
    asm volatile("ldmatrix.sync.aligned.m8n8.x4.shared.b16 {%0,%1,%2,%3}, [%4];"
        : "=r"(r[0]), "=r"(r[1]), "=r"(r[2]), "=r"(r[3]) : "r"(addr));
}
__device__ __forceinline__ void mma_bf16(float* d, const uint32_t* a, const uint32_t* b) {
    asm volatile("mma.sync.aligned.m16n8k16.row.col.f32.bf16.bf16.f32 "
        "{%0,%1,%2,%3}, {%4,%5,%6,%7}, {%8,%9}, {%0,%1,%2,%3};"
        : "+f"(d[0]), "+f"(d[1]), "+f"(d[2]), "+f"(d[3])
        : "r"(a[0]), "r"(a[1]), "r"(a[2]), "r"(a[3]), "r"(b[0]), "r"(b[1]));
}
__device__ __forceinline__ void cp_async16(uint32_t dst, const void* src) {
    asm volatile("cp.async.cg.shared.global [%0], [%1], 16;" :: "r"(dst), "l"(src));
}
#define CP_COMMIT()  asm volatile("cp.async.commit_group;" ::: "memory")
#define CP_WAIT0()   asm volatile("cp.async.wait_group 0;" ::: "memory")

// smem byte offsets
#define OFF_F0     0
#define OFF_F1     512
#define OFF_MASK   1024
#define OFF_SOUT2  1280
#define OFF_SEXP   1792        /* [2][256] floats = 2048 B */
#define OFF_BIM    3840
#define OFF_WT0    5888
#define OFF_WT1    7936
#define OFF_BT     9984
#define OFF_A      12288       /* A: [128][512] bf16 swizzled = 131072 B */
#define OFF_B      143360      /* B: 2 x 32768 double buffer             */
#define SMEM_BYTES 208896

// ---------------------------------------------------------------------------
// Kernel: embedding GEMMs via packed f32x2 FFMA. 128 blocks x 8 rows.
// Thread owns a column PAIR (2c, 2c+1) for 4 rows, both GEMMs.
// ---------------------------------------------------------------------------
__global__ __launch_bounds__(512) void embed_kernel(
    const float* __restrict__ x,
    const float* __restrict__ Wp, const float* __restrict__ bp,
    const float* __restrict__ Wx, const float* __restrict__ bx)
{
    __shared__ float xs[8 * CC];
    const int tid = threadIdx.x;
    const int r0  = blockIdx.x * 8;
    for (int idx = tid; idx < 8 * CC; idx += 512) xs[idx] = x[r0 * CC + idx];
    __syncthreads();

    const int rg = (tid >> 8) * 4;            // rows rg..rg+3
    const int cp = tid & 255;                 // column pair index
    const unsigned long long* WpU = (const unsigned long long*)Wp;
    const unsigned long long* WxU = (const unsigned long long*)Wx;

    unsigned long long accP[4], accX[4];
#pragma unroll
    for (int r = 0; r < 4; r++) { accP[r] = 0ull; accX[r] = 0ull; }

#pragma unroll 4
    for (int k = 0; k < CC; k++) {
        const unsigned long long wp2 = WpU[k * 256 + cp];
        const unsigned long long wx2 = WxU[k * 256 + cp];
#pragma unroll
        for (int r = 0; r < 4; r++) {
            const float xv = xs[(rg + r) * CC + k];
            unsigned long long xp;
            asm("mov.b64 %0, {%1, %1};" : "=l"(xp) : "r"(__float_as_uint(xv)));
            asm("fma.rn.f32x2 %0, %1, %2, %0;" : "+l"(accP[r]) : "l"(xp), "l"(wp2));
            asm("fma.rn.f32x2 %0, %1, %2, %0;" : "+l"(accX[r]) : "l"(xp), "l"(wx2));
        }
    }

    const float2 bp2 = *(const float2*)(bp + cp * 2);
    const float2 bx2 = *(const float2*)(bx + cp * 2);
#pragma unroll
    for (int r = 0; r < 4; r++) {
        uint32_t lo, hi;
        asm("mov.b64 {%0, %1}, %2;" : "=r"(lo), "=r"(hi) : "l"(accP[r]));
        *(float2*)(g_VE + (size_t)(r0 + rg + r) * CC + cp * 2) =
            make_float2(__uint_as_float(lo) + bp2.x, __uint_as_float(hi) + bp2.y);
        asm("mov.b64 {%0, %1}, %2;" : "=r"(lo), "=r"(hi) : "l"(accX[r]));
        *(float2*)(g_XE + (size_t)(r0 + rg + r) * CC + cp * 2) =
            make_float2(__uint_as_float(lo) + bx2.x, __uint_as_float(hi) + bx2.y);
    }
}

// ---------------------------------------------------------------------------
// Kernel: W_imp -> transposed bf16 [N][K]
// ---------------------------------------------------------------------------
__global__ void prep_wim_kernel(const float* __restrict__ Wim)
{
    __shared__ float tile[32][33];
    const int n0 = blockIdx.x * 32, k0 = blockIdx.y * 32;
    tile[threadIdx.y][threadIdx.x] = Wim[(k0 + threadIdx.y) * CC + n0 + threadIdx.x];
    __syncthreads();
    g_WimT[(n0 + threadIdx.y) * CC + k0 + threadIdx.x] =
        __float2bfloat16(tile[threadIdx.x][threadIdx.y]);
}

// ---------------------------------------------------------------------------
// Main fused kernel: one CTA per (b, i-pair). M=128, K=512, N=512 in
// 2 chunks of 256. 512 threads = 16 warps (4 mw x 4 nw), warp tile 32m x 64n,
// mma.sync m16n8k16 bf16, ONE sync per K-stage, register-resident epilogue.
// ---------------------------------------------------------------------------
__global__ __launch_bounds__(512, 1) void temporal_kernel(
    const float* __restrict__ x,
    const float* __restrict__ ts,
    const float* __restrict__ amask,
    const float* __restrict__ Wt,  const float* __restrict__ bt,
    const float* __restrict__ bim,
    float* __restrict__ out)
{
    extern __shared__ char sm[];
    const uint32_t smb = smem_u32(sm);
    const int tid  = threadIdx.x;
    const int lane = tid & 31;
    const int wid  = tid >> 5;

    const int b    = blockIdx.x >> 5;
    const int pair = blockIdx.x & 31;
    const int i0   = pair * 2;

    // ---- B stage loader: stage = [256 n][64 k] bf16 = 32 KB, XOR-swizzled ----
    auto issueB = [&](int ch, int s) {
        const int n  = tid >> 1;
        const int cq = (tid & 1) * 4;
        const uint32_t dstRow = smb + OFF_B + (s & 1) * 32768 + n * 128;
        const __nv_bfloat16* src = g_WimT + (size_t)(ch * 256 + n) * CC + s * 64 + cq * 8;
#pragma unroll
        for (int c = 0; c < 4; c++)
            cp_async16(dstRow + (((cq + c) ^ (n & 7)) << 4), src + c * 8);
        CP_COMMIT();
    };
    issueB(0, 0);   // in flight during staging + A-build

    float* f0s   = (float*)(sm + OFF_F0);
    float* f1s   = (float*)(sm + OFF_F1);
    float* maskv = (float*)(sm + OFF_MASK);
    float* sout2 = (float*)(sm + OFF_SOUT2);
    float* sexp  = (float*)(sm + OFF_SEXP);    // [2][256]
    float* sbim  = (float*)(sm + OFF_BIM);
    float* sWt0  = (float*)(sm + OFF_WT0);
    float* sWt1  = (float*)(sm + OFF_WT1);
    float* sbt   = (float*)(sm + OFF_BT);

    // ---- staging ----
    sbim[tid] = bim[tid];
    sWt0[tid] = Wt[tid];
    sWt1[tid] = Wt[CC + tid];
    sbt[tid]  = bt[tid];
    if (tid < 128) {
        const int ih = tid >> 6, jj = tid & 63;
        const float rel = ts[b * TT + i0 + ih] - ts[b * TT + jj];
        f0s[tid] = log1pf(fmaxf(rel, 0.f));
        f1s[tid] = log1pf(fmaxf(-rel, 0.f));
        sout2[tid] = 0.f;
    }
    if (tid < 64) maskv[tid] = amask[b * TT + tid];
    sexp[tid] = 0.f;
    __syncthreads();

    // ---- build A = relu(h) [128 m][512 k] bf16, XOR-swizzled 16B chunks ----
    {
        const int rbase = wid * 8;
#pragma unroll
        for (int rr = 0; rr < 8; rr++) {
            const int r = rbase + rr;
            const float f0v = f0s[r], f1v = f1s[r];
            const float* XEr = g_XE + (size_t)(b * TT + (r & 63)) * CC;
            char* Arow = sm + OFF_A + r * 1024;
            const int xr = r & 7;
#pragma unroll
            for (int pass = 0; pass < 4; pass++) {
                const int k = pass * 128 + lane * 4;
                const float4 xe = *(const float4*)(XEr + k);
                const float4 w0 = *(const float4*)(sWt0 + k);
                const float4 w1 = *(const float4*)(sWt1 + k);
                const float4 bb = *(const float4*)(sbt + k);
                const float h0 = fmaxf(fmaf(f0v, w0.x, fmaf(f1v, w1.x, bb.x)) + xe.x, 0.f);
                const float h1 = fmaxf(fmaf(f0v, w0.y, fmaf(f1v, w1.y, bb.y)) + xe.y, 0.f);
                const float h2 = fmaxf(fmaf(f0v, w0.z, fmaf(f1v, w1.z, bb.z)) + xe.z, 0.f);
                const float h3 = fmaxf(fmaf(f0v, w0.w, fmaf(f1v, w1.w, bb.w)) + xe.w, 0.f);
                uint2 pk;
                ((__nv_bfloat162*)&pk)[0] = __floats2bfloat162_rn(h0, h1);
                ((__nv_bfloat162*)&pk)[1] = __floats2bfloat162_rn(h2, h3);
                const int c8 = pass * 16 + (lane >> 1);
                *(uint2*)(Arow + ((c8 ^ xr) << 4) + ((lane & 1) << 3)) = pk;
            }
        }
    }

    // ---- warp/lane geometry ----
    const int mw = wid & 3, nw = wid >> 2;
    const int m0  = mw * 32;
    const int n0w = nw * 64;
    const int mA  = m0 + (lane & 15);
    const int aC8 = lane >> 4;
    const int aXr = mA & 7;
    const uint32_t aBase = smb + OFF_A + mA * 1024;
    const int nB  = n0w + (lane & 7) + ((lane >> 4) << 3);
    const int bC8 = (lane >> 3) & 1;
    const int bXr = nB & 7;
    const uint32_t bRowOff = (uint32_t)nB * 128;
    const int qrow = lane >> 2, qcol2 = (lane & 3) * 2;
    const int ihl  = mw >> 1;

#pragma unroll 1
    for (int ch = 0; ch < 2; ch++) {
        float acc[2][8][4];
#pragma unroll
        for (int mf = 0; mf < 2; mf++)
#pragma unroll
            for (int nf = 0; nf < 8; nf++)
#pragma unroll
                for (int d = 0; d < 4; d++) acc[mf][nf][d] = 0.f;

#pragma unroll 1
        for (int s = 0; s < 8; s++) {
            CP_WAIT0();          // stage s data (issued one stage ago) complete
            __syncthreads();     // visible to all warps; prior MMAs done
            if (s < 7)            issueB(ch, s + 1);      // overlaps MMA below
            else if (ch < 1)      issueB(ch + 1, 0);      // overlaps epilogue too
            const uint32_t Bslot = smb + OFF_B + (s & 1) * 32768;
#pragma unroll
            for (int t = 0; t < 4; t++) {
                uint32_t a0[4], a1[4], bf[4][4];
                const uint32_t swA = (uint32_t)(((s * 8 + t * 2 + aC8) ^ aXr) << 4);
                ldsm4(a0, aBase + swA);
                ldsm4(a1, aBase + 16384 + swA);
                const uint32_t swB = (uint32_t)(((t * 2 + bC8) ^ bXr) << 4);
                const uint32_t bA = Bslot + bRowOff + swB;
                ldsm4(bf[0], bA);
                ldsm4(bf[1], bA + 2048);
                ldsm4(bf[2], bA + 4096);
                ldsm4(bf[3], bA + 6144);
#pragma unroll
                for (int q = 0; q < 4; q++) {
                    mma_bf16(acc[0][q * 2],     a0, bf[q]);
                    mma_bf16(acc[0][q * 2 + 1], a0, bf[q] + 2);
                    mma_bf16(acc[1][q * 2],     a1, bf[q]);
                    mma_bf16(acc[1][q * 2 + 1], a1, bf[q] + 2);
                }
            }
        }
        __syncthreads();   // last stage's MMAs complete before epilogue reuse

        // ---- register epilogue (two n-halves to cap register pressure) ----
        float rs[4] = {0.f, 0.f, 0.f, 0.f};
#pragma unroll
        for (int nh = 0; nh < 2; nh++) {
            float bimv[8], cs[8];
#pragma unroll
            for (int nf = 0; nf < 4; nf++) {
                bimv[nf * 2]     = sbim[ch * 256 + n0w + nh * 32 + nf * 8 + qcol2];
                bimv[nf * 2 + 1] = sbim[ch * 256 + n0w + nh * 32 + nf * 8 + qcol2 + 1];
                cs[nf * 2] = 0.f; cs[nf * 2 + 1] = 0.f;
            }
#pragma unroll
            for (int mf = 0; mf < 2; mf++) {
#pragma unroll
                for (int h = 0; h < 2; h++) {
                    const int r  = m0 + mf * 16 + h * 8 + qrow;
                    const float mk = maskv[r & 63];
                    const float* VEr = g_VE + (size_t)(b * TT + (r & 63)) * CC
                                       + ch * 256 + n0w + nh * 32 + qcol2;
                    float rsum = 0.f;
#pragma unroll
                    for (int nf = 0; nf < 4; nf++) {
                        const float2 ve = *(const float2*)(VEr + nf * 8);
                        const float s0 = acc[mf][nh * 4 + nf][h * 2 + 0] + bimv[nf * 2];
                        const float s1 = acc[mf][nh * 4 + nf][h * 2 + 1] + bimv[nf * 2 + 1];
                        const float p0 = __fdividef(mk, 1.f + __expf(-s0));
                        const float p1 = __fdividef(mk, 1.f + __expf(-s1));
                        rsum += p0 + p1;
                        cs[nf * 2]     += __expf(ve.x * p0);
                        cs[nf * 2 + 1] += __expf(ve.y * p1);
                    }
                    rs[mf * 2 + h] += rsum;
                }
            }
            // column exp-sums -> sexp (reduce over the 8 qrow lanes)
#pragma unroll
            for (int c = 0; c < 8; c++) {
                cs[c] += __shfl_xor_sync(0xffffffffu, cs[c], 4);
                cs[c] += __shfl_xor_sync(0xffffffffu, cs[c], 8);
                cs[c] += __shfl_xor_sync(0xffffffffu, cs[c], 16);
            }
            if (lane < 4) {
#pragma unroll
                for (int nf = 0; nf < 4; nf++) {
                    atomicAdd(&sexp[ihl * 256 + n0w + nh * 32 + nf * 8 + lane * 2],     cs[nf * 2]);
                    atomicAdd(&sexp[ihl * 256 + n0w + nh * 32 + nf * 8 + lane * 2 + 1], cs[nf * 2 + 1]);
                }
            }
        }
        // row sums -> sout2 (reduce over the 4 qcol lanes)
#pragma unroll
        for (int q = 0; q < 4; q++) {
            rs[q] += __shfl_xor_sync(0xffffffffu, rs[q], 1);
            rs[q] += __shfl_xor_sync(0xffffffffu, rs[q], 2);
        }
        if ((lane & 3) == 0) {
#pragma unroll
            for (int q = 0; q < 4; q++)
                atomicAdd(&sout2[m0 + (q >> 1) * 16 + (q & 1) * 8 + qrow], rs[q]);
        }
        __syncthreads();

        // out1 = x + log(sum_j exp(z)) for this chunk's 2 x 256 columns
        {
            const int ih = tid >> 8, cl = tid & 255;
            const int ng = ch * 256 + cl;
            const int row = b * TT + i0 + ih;
            out[(size_t)row * CC + ng] = x[(size_t)row * CC + ng] + __logf(sexp[tid]);
            sexp[tid] = 0.f;
        }
        __syncthreads();
    }

    // ---- out2: mean over C ----
    if (tid < 128) {
        const int ih = tid >> 6, j = tid & 63;
        out[BB * TT * CC + ((b * TT + i0 + ih) * TT + j)] = sout2[tid] * (1.f / 512.f);
    }
}

// ---------------------------------------------------------------------------
extern "C" void kernel_launch(void* const* d_in, const int* in_sizes, int n_in,
                              void* d_out, int out_size)
{
    const float* x     = (const float*)d_in[0];
    const float* ts    = (const float*)d_in[1];
    const float* amask = (const float*)d_in[2];
    const float* Wp    = (const float*)d_in[3];
    const float* bp    = (const float*)d_in[4];
    const float* Wx    = (const float*)d_in[5];
    const float* bx    = (const float*)d_in[6];
    const float* Wt    = (const float*)d_in[7];
    const float* bt    = (const float*)d_in[8];
    const float* Wim   = (const float*)d_in[9];
    const float* bim   = (const float*)d_in[10];
    float* out = (float*)d_out;

    prep_wim_kernel<<<dim3(16, 16), dim3(32, 32)>>>(Wim);
    embed_kernel<<<128, 512>>>(x, Wp, bp, Wx, bx);

    cudaFuncSetAttribute(temporal_kernel, cudaFuncAttributeMaxDynamicSharedMemorySize, SMEM_BYTES);
    temporal_kernel<<<BB * 32, 512, SMEM_BYTES>>>(x, ts, amask, Wt, bt, bim, out);
}

// round 10
// speedup vs baseline: 5.3882x; 1.3091x over previous
#include <cuda_runtime.h>
#include <cuda_bf16.h>
#include <cstdint>

#define BB 16
#define TT 64
#define CC 512

// ---------------------------------------------------------------------------
// Device scratch (allocation-free rule)
// ---------------------------------------------------------------------------
__device__ float g_VE[BB * TT * CC];              // x @ W_proj + b_proj
__device__ float g_XE[BB * TT * CC];              // x @ W_x    + b_x
__device__ __nv_bfloat16 g_WT[3 * CC * CC];       // [Wim^T | Wp^T | Wx^T] bf16 [N][K]

// ---------------------------------------------------------------------------
// Helpers (baseline sm_80+ PTX: mma.sync / ldmatrix / cp.async / tanh.approx)
// ---------------------------------------------------------------------------
__device__ __forceinline__ uint32_t smem_u32(const void* p) {
    uint32_t a;
    asm("{ .reg .u64 t; cvta.to.shared.u64 t, %1; cvt.u32.u64 %0, t; }" : "=r"(a) : "l"(p));
    return a;
}
__device__ __forceinline__ void ldsm4(uint32_t* r, uint32_t addr) {
    asm volatile("ldmatrix.sync.aligned.m8n8.x4.shared.b16 {%0,%1,%2,%3}, [%4];"
        : "=r"(r[0]), "=r"(r[1]), "=r"(r[2]), "=r"(r[3]) : "r"(addr));
}
__device__ __forceinline__ void mma_bf16(float* d, const uint32_t* a, const uint32_t* b) {
    asm volatile("mma.sync.aligned.m16n8k16.row.col.f32.bf16.bf16.f32 "
        "{%0,%1,%2,%3}, {%4,%5,%6,%7}, {%8,%9}, {%0,%1,%2,%3};"
        : "+f"(d[0]), "+f"(d[1]), "+f"(d[2]), "+f"(d[3])
        : "r"(a[0]), "r"(a[1]), "r"(a[2]), "r"(a[3]), "r"(b[0]), "r"(b[1]));
}
__device__ __forceinline__ void cp_async16(uint32_t dst, const void* src) {
    asm volatile("cp.async.cg.shared.global [%0], [%1], 16;" :: "r"(dst), "l"(src));
}
__device__ __forceinline__ float tanh_fast(float v) {
    float y;
    asm("tanh.approx.f32 %0, %1;" : "=f"(y) : "f"(v));
    return y;
}
#define CP_COMMIT()  asm volatile("cp.async.commit_group;" ::: "memory")
#define CP_WAIT0()   asm volatile("cp.async.wait_group 0;" ::: "memory")

// temporal smem byte offsets
#define OFF_F0     0
#define OFF_F1     512
#define OFF_MASK   1024
#define OFF_SOUT2  1280
#define OFF_SEXP   1792        /* [2][256] floats = 2048 B */
#define OFF_BIM    3840
#define OFF_WT0    5888
#define OFF_WT1    7936
#define OFF_BT     9984
#define OFF_A      12288       /* A: [128][512] bf16 swizzled = 131072 B */
#define OFF_B      143360      /* B: 2 x 32768 double buffer             */
#define SMEM_BYTES 208896

// embed_mma smem: A [64][512] bf16 = 64 KB, B 2 x 16 KB
#define EMB_OFF_B   65536
#define EMB_SMEM    98304

// ---------------------------------------------------------------------------
// Kernel: transpose + cvt all three weight matrices to bf16 [N][K]
// grid (16,16,3), block (32,32). z: 0=Wim, 1=Wp, 2=Wx.
// ---------------------------------------------------------------------------
__global__ void prep_w_kernel(const float* __restrict__ Wim,
                              const float* __restrict__ Wp,
                              const float* __restrict__ Wx)
{
    __shared__ float tile[32][33];
    const int z = blockIdx.z;
    const float* src = (z == 0) ? Wim : (z == 1) ? Wp : Wx;
    const int n0 = blockIdx.x * 32, k0 = blockIdx.y * 32;
    tile[threadIdx.y][threadIdx.x] = src[(k0 + threadIdx.y) * CC + n0 + threadIdx.x];
    __syncthreads();
    g_WT[(size_t)(z * CC + n0 + threadIdx.y) * CC + k0 + threadIdx.x] =
        __float2bfloat16(tile[threadIdx.x][threadIdx.y]);
}

// ---------------------------------------------------------------------------
// Kernel: embedding GEMMs on tensor cores.
// out[1024, 1024] = x[1024, 512] @ [Wp | Wx][512, 1024]  (bf16, fp32 accum)
// Grid 128 CTAs: mt = blk&15 (64 rows), nt = blk>>4 (128 cols of concat N).
// 256 threads = 8 warps (2 mw x 4 nw), warp tile 32m x 32n.
// ---------------------------------------------------------------------------
__global__ __launch_bounds__(256, 2) void embed_mma_kernel(
    const float* __restrict__ x,
    const float* __restrict__ bp, const float* __restrict__ bx)
{
    extern __shared__ char sm[];
    const uint32_t smb = smem_u32(sm);
    const int tid = threadIdx.x, lane = tid & 31, wid = tid >> 5;
    const int mt = blockIdx.x & 15, nt = blockIdx.x >> 4;
    const int r0 = mt * 64;

    auto issueB = [&](int s) {
        const int n  = tid >> 1;
        const int cq = (tid & 1) * 4;
        const uint32_t dstRow = smb + EMB_OFF_B + (s & 1) * 16384 + n * 128;
        const __nv_bfloat16* src = g_WT + (size_t)(CC + nt * 128 + n) * CC + s * 64 + cq * 8;
#pragma unroll
        for (int c = 0; c < 4; c++)
            cp_async16(dstRow + (((cq + c) ^ (n & 7)) << 4), src + c * 8);
        CP_COMMIT();
    };
    issueB(0);

    // A = x rows [r0, r0+64) cvt to bf16, swizzled (overlaps B load)
    {
        const int rbase = wid * 8;
#pragma unroll
        for (int rr = 0; rr < 8; rr++) {
            const int r = rbase + rr;
            const float* xr = x + (size_t)(r0 + r) * CC;
            char* Arow = sm + r * 1024;
            const int xw = r & 7;
#pragma unroll
            for (int pass = 0; pass < 4; pass++) {
                const int k = pass * 128 + lane * 4;
                const float4 xv = *(const float4*)(xr + k);
                uint2 pk;
                ((__nv_bfloat162*)&pk)[0] = __floats2bfloat162_rn(xv.x, xv.y);
                ((__nv_bfloat162*)&pk)[1] = __floats2bfloat162_rn(xv.z, xv.w);
                const int c8 = pass * 16 + (lane >> 1);
                *(uint2*)(Arow + ((c8 ^ xw) << 4) + ((lane & 1) << 3)) = pk;
            }
        }
    }

    const int mw = wid & 1, nw = wid >> 1;
    const int mA  = mw * 32 + (lane & 15);
    const int aC8 = lane >> 4;
    const int aXr = mA & 7;
    const uint32_t aBase = smb + mA * 1024;
    const int nB  = nw * 32 + (lane & 7) + ((lane >> 4) << 3);
    const int bC8 = (lane >> 3) & 1;
    const int bXr = nB & 7;
    const uint32_t bRowOff = (uint32_t)nB * 128;

    float acc[2][4][4];
#pragma unroll
    for (int mf = 0; mf < 2; mf++)
#pragma unroll
        for (int nf = 0; nf < 4; nf++)
#pragma unroll
            for (int d = 0; d < 4; d++) acc[mf][nf][d] = 0.f;

#pragma unroll 1
    for (int s = 0; s < 8; s++) {
        CP_WAIT0();
        __syncthreads();
        if (s < 7) issueB(s + 1);
        const uint32_t Bslot = smb + EMB_OFF_B + (s & 1) * 16384;
#pragma unroll
        for (int t = 0; t < 4; t++) {
            uint32_t a0[4], a1[4], b0[4], b1[4];
            const uint32_t swA = (uint32_t)(((s * 8 + t * 2 + aC8) ^ aXr) << 4);
            ldsm4(a0, aBase + swA);
            ldsm4(a1, aBase + 16384 + swA);
            const uint32_t swB = (uint32_t)(((t * 2 + bC8) ^ bXr) << 4);
            const uint32_t bA = Bslot + bRowOff + swB;
            ldsm4(b0, bA);
            ldsm4(b1, bA + 2048);
            mma_bf16(acc[0][0], a0, b0);
            mma_bf16(acc[0][1], a0, b0 + 2);
            mma_bf16(acc[0][2], a0, b1);
            mma_bf16(acc[0][3], a0, b1 + 2);
            mma_bf16(acc[1][0], a1, b0);
            mma_bf16(acc[1][1], a1, b0 + 2);
            mma_bf16(acc[1][2], a1, b1);
            mma_bf16(acc[1][3], a1, b1 + 2);
        }
    }

    // epilogue: +bias, write fp32. CTA-uniform destination matrix.
    const float* bias = (nt < 4) ? bp : bx;
    float* dst        = (nt < 4) ? g_VE : g_XE;
    const int qrow = lane >> 2, qcol2 = (lane & 3) * 2;
    const int cbase = (nt & 3) * 128 + nw * 32;
    float2 bb[4];
#pragma unroll
    for (int nf = 0; nf < 4; nf++)
        bb[nf] = *(const float2*)(bias + cbase + nf * 8 + qcol2);
#pragma unroll
    for (int mf = 0; mf < 2; mf++)
#pragma unroll
        for (int h = 0; h < 2; h++) {
            const int row = r0 + mw * 32 + mf * 16 + h * 8 + qrow;
#pragma unroll
            for (int nf = 0; nf < 4; nf++) {
                const int col = cbase + nf * 8 + qcol2;
                *(float2*)(dst + (size_t)row * CC + col) =
                    make_float2(acc[mf][nf][h * 2] + bb[nf].x,
                                acc[mf][nf][h * 2 + 1] + bb[nf].y);
            }
        }
}

// ---------------------------------------------------------------------------
// Main fused kernel: one CTA per (b, i-pair). M=128, K=512, N=512 in
// 2 chunks of 256. 512 threads = 16 warps (4 mw x 4 nw), warp tile 32m x 64n,
// mma.sync m16n8k16 bf16, ONE sync per K-stage, register-resident epilogue.
// ---------------------------------------------------------------------------
__global__ __launch_bounds__(512, 1) void temporal_kernel(
    const float* __restrict__ x,
    const float* __restrict__ ts,
    const float* __restrict__ amask,
    const float* __restrict__ Wt,  const float* __restrict__ bt,
    const float* __restrict__ bim,
    float* __restrict__ out)
{
    extern __shared__ char sm[];
    const uint32_t smb = smem_u32(sm);
    const int tid  = threadIdx.x;
    const int lane = tid & 31;
    const int wid  = tid >> 5;

    const int b    = blockIdx.x >> 5;
    const int pair = blockIdx.x & 31;
    const int i0   = pair * 2;

    // B stage loader: stage = [256 n][64 k] bf16 = 32 KB, XOR-swizzled
    auto issueB = [&](int ch, int s) {
        const int n  = tid >> 1;
        const int cq = (tid & 1) * 4;
        const uint32_t dstRow = smb + OFF_B + (s & 1) * 32768 + n * 128;
        const __nv_bfloat16* src = g_WT + (size_t)(ch * 256 + n) * CC + s * 64 + cq * 8;
#pragma unroll
        for (int c = 0; c < 4; c++)
            cp_async16(dstRow + (((cq + c) ^ (n & 7)) << 4), src + c * 8);
        CP_COMMIT();
    };
    issueB(0, 0);   // in flight during staging + A-build

    float* f0s   = (float*)(sm + OFF_F0);
    float* f1s   = (float*)(sm + OFF_F1);
    float* maskv = (float*)(sm + OFF_MASK);
    float* sout2 = (float*)(sm + OFF_SOUT2);
    float* sexp  = (float*)(sm + OFF_SEXP);    // [2][256]
    float* sbim  = (float*)(sm + OFF_BIM);
    float* sWt0  = (float*)(sm + OFF_WT0);
    float* sWt1  = (float*)(sm + OFF_WT1);
    float* sbt   = (float*)(sm + OFF_BT);

    // ---- staging ----
    sbim[tid] = bim[tid];
    sWt0[tid] = Wt[tid];
    sWt1[tid] = Wt[CC + tid];
    sbt[tid]  = bt[tid];
    if (tid < 128) {
        const int ih = tid >> 6, jj = tid & 63;
        const float rel = ts[b * TT + i0 + ih] - ts[b * TT + jj];
        f0s[tid] = log1pf(fmaxf(rel, 0.f));
        f1s[tid] = log1pf(fmaxf(-rel, 0.f));
        sout2[tid] = 0.f;
    }
    if (tid < 64) maskv[tid] = amask[b * TT + tid];
    sexp[tid] = 0.f;
    __syncthreads();

    // ---- build A = relu(h) [128 m][512 k] bf16, XOR-swizzled 16B chunks ----
    {
        const int rbase = wid * 8;
#pragma unroll
        for (int rr = 0; rr < 8; rr++) {
            const int r = rbase + rr;
            const float f0v = f0s[r], f1v = f1s[r];
            const float* XEr = g_XE + (size_t)(b * TT + (r & 63)) * CC;
            char* Arow = sm + OFF_A + r * 1024;
            const int xr = r & 7;
#pragma unroll
            for (int pass = 0; pass < 4; pass++) {
                const int k = pass * 128 + lane * 4;
                const float4 xe = *(const float4*)(XEr + k);
                const float4 w0 = *(const float4*)(sWt0 + k);
                const float4 w1 = *(const float4*)(sWt1 + k);
                const float4 bbv = *(const float4*)(sbt + k);
                const float h0 = fmaxf(fmaf(f0v, w0.x, fmaf(f1v, w1.x, bbv.x)) + xe.x, 0.f);
                const float h1 = fmaxf(fmaf(f0v, w0.y, fmaf(f1v, w1.y, bbv.y)) + xe.y, 0.f);
                const float h2 = fmaxf(fmaf(f0v, w0.z, fmaf(f1v, w1.z, bbv.z)) + xe.z, 0.f);
                const float h3 = fmaxf(fmaf(f0v, w0.w, fmaf(f1v, w1.w, bbv.w)) + xe.w, 0.f);
                uint2 pk;
                ((__nv_bfloat162*)&pk)[0] = __floats2bfloat162_rn(h0, h1);
                ((__nv_bfloat162*)&pk)[1] = __floats2bfloat162_rn(h2, h3);
                const int c8 = pass * 16 + (lane >> 1);
                *(uint2*)(Arow + ((c8 ^ xr) << 4) + ((lane & 1) << 3)) = pk;
            }
        }
    }

    // ---- warp/lane geometry ----
    const int mw = wid & 3, nw = wid >> 2;
    const int m0  = mw * 32;
    const int n0w = nw * 64;
    const int mA  = m0 + (lane & 15);
    const int aC8 = lane >> 4;
    const int aXr = mA & 7;
    const uint32_t aBase = smb + OFF_A + mA * 1024;
    const int nB  = n0w + (lane & 7) + ((lane >> 4) << 3);
    const int bC8 = (lane >> 3) & 1;
    const int bXr = nB & 7;
    const uint32_t bRowOff = (uint32_t)nB * 128;
    const int qrow = lane >> 2, qcol2 = (lane & 3) * 2;
    const int ihl  = mw >> 1;

#pragma unroll 1
    for (int ch = 0; ch < 2; ch++) {
        float acc[2][8][4];
#pragma unroll
        for (int mf = 0; mf < 2; mf++)
#pragma unroll
            for (int nf = 0; nf < 8; nf++)
#pragma unroll
                for (int d = 0; d < 4; d++) acc[mf][nf][d] = 0.f;

#pragma unroll 1
        for (int s = 0; s < 8; s++) {
            CP_WAIT0();          // stage s data complete
            __syncthreads();     // all warps past MMAs reading the other slot
            if (s < 7)            issueB(ch, s + 1);      // overlaps MMA below
            else if (ch < 1)      issueB(ch + 1, 0);      // overlaps epilogue too
            const uint32_t Bslot = smb + OFF_B + (s & 1) * 32768;
#pragma unroll
            for (int t = 0; t < 4; t++) {
                uint32_t a0[4], a1[4], bf[4][4];
                const uint32_t swA = (uint32_t)(((s * 8 + t * 2 + aC8) ^ aXr) << 4);
                ldsm4(a0, aBase + swA);
                ldsm4(a1, aBase + 16384 + swA);
                const uint32_t swB = (uint32_t)(((t * 2 + bC8) ^ bXr) << 4);
                const uint32_t bA = Bslot + bRowOff + swB;
                ldsm4(bf[0], bA);
                ldsm4(bf[1], bA + 2048);
                ldsm4(bf[2], bA + 4096);
                ldsm4(bf[3], bA + 6144);
#pragma unroll
                for (int q = 0; q < 4; q++) {
                    mma_bf16(acc[0][q * 2],     a0, bf[q]);
                    mma_bf16(acc[0][q * 2 + 1], a0, bf[q] + 2);
                    mma_bf16(acc[1][q * 2],     a1, bf[q]);
                    mma_bf16(acc[1][q * 2 + 1], a1, bf[q] + 2);
                }
            }
        }
        __syncthreads();   // last stage's MMAs complete before epilogue reuse

        // ---- register epilogue (two n-halves), sigmoid via tanh.approx ----
        float rs[4] = {0.f, 0.f, 0.f, 0.f};
#pragma unroll
        for (int nh = 0; nh < 2; nh++) {
            float bimv[8], cs[8];
#pragma unroll
            for (int nf = 0; nf < 4; nf++) {
                bimv[nf * 2]     = sbim[ch * 256 + n0w + nh * 32 + nf * 8 + qcol2];
                bimv[nf * 2 + 1] = sbim[ch * 256 + n0w + nh * 32 + nf * 8 + qcol2 + 1];
                cs[nf * 2] = 0.f; cs[nf * 2 + 1] = 0.f;
            }
#pragma unroll
            for (int mf = 0; mf < 2; mf++) {
#pragma unroll
                for (int h = 0; h < 2; h++) {
                    const int r  = m0 + mf * 16 + h * 8 + qrow;
                    const float hmk = 0.5f * maskv[r & 63];
                    const float* VEr = g_VE + (size_t)(b * TT + (r & 63)) * CC
                                       + ch * 256 + n0w + nh * 32 + qcol2;
                    float rsum = 0.f;
#pragma unroll
                    for (int nf = 0; nf < 4; nf++) {
                        const float2 ve = *(const float2*)(VEr + nf * 8);
                        const float s0 = acc[mf][nh * 4 + nf][h * 2 + 0] + bimv[nf * 2];
                        const float s1 = acc[mf][nh * 4 + nf][h * 2 + 1] + bimv[nf * 2 + 1];
                        // sigmoid(s)*mk = hmk + hmk*tanh(s/2)
                        const float p0 = fmaf(tanh_fast(0.5f * s0), hmk, hmk);
                        const float p1 = fmaf(tanh_fast(0.5f * s1), hmk, hmk);
                        rsum += p0 + p1;
                        cs[nf * 2]     += __expf(ve.x * p0);
                        cs[nf * 2 + 1] += __expf(ve.y * p1);
                    }
                    rs[mf * 2 + h] += rsum;
                }
            }
            // column exp-sums -> sexp (reduce over the 8 qrow lanes)
#pragma unroll
            for (int c = 0; c < 8; c++) {
                cs[c] += __shfl_xor_sync(0xffffffffu, cs[c], 4);
                cs[c] += __shfl_xor_sync(0xffffffffu, cs[c], 8);
                cs[c] += __shfl_xor_sync(0xffffffffu, cs[c], 16);
            }
            if (lane < 4) {
#pragma unroll
                for (int nf = 0; nf < 4; nf++) {
                    atomicAdd(&sexp[ihl * 256 + n0w + nh * 32 + nf * 8 + lane * 2],     cs[nf * 2]);
                    atomicAdd(&sexp[ihl * 256 + n0w + nh * 32 + nf * 8 + lane * 2 + 1], cs[nf * 2 + 1]);
                }
            }
        }
        // row sums -> sout2 (reduce over the 4 qcol lanes)
#pragma unroll
        for (int q = 0; q < 4; q++) {
            rs[q] += __shfl_xor_sync(0xffffffffu, rs[q], 1);
            rs[q] += __shfl_xor_sync(0xffffffffu, rs[q], 2);
        }
        if ((lane & 3) == 0) {
#pragma unroll
            for (int q = 0; q < 4; q++)
                atomicAdd(&sout2[m0 + (q >> 1) * 16 + (q & 1) * 8 + qrow], rs[q]);
        }
        __syncthreads();

        // out1 = x + log(sum_j exp(z)) for this chunk's 2 x 256 columns
        {
            const int ih = tid >> 8, cl = tid & 255;
            const int ng = ch * 256 + cl;
            const int row = b * TT + i0 + ih;
            out[(size_t)row * CC + ng] = x[(size_t)row * CC + ng] + __logf(sexp[tid]);
            sexp[tid] = 0.f;
        }
        __syncthreads();
    }

    // ---- out2: mean over C ----
    if (tid < 128) {
        const int ih = tid >> 6, j = tid & 63;
        out[BB * TT * CC + ((b * TT + i0 + ih) * TT + j)] = sout2[tid] * (1.f / 512.f);
    }
}

// ---------------------------------------------------------------------------
extern "C" void kernel_launch(void* const* d_in, const int* in_sizes, int n_in,
                              void* d_out, int out_size)
{
    const float* x     = (const float*)d_in[0];
    const float* ts    = (const float*)d_in[1];
    const float* amask = (const float*)d_in[2];
    const float* Wp    = (const float*)d_in[3];
    const float* bp    = (const float*)d_in[4];
    const float* Wx    = (const float*)d_in[5];
    const float* bx    = (const float*)d_in[6];
    const float* Wt    = (const float*)d_in[7];
    const float* bt    = (const float*)d_in[8];
    const float* Wim   = (const float*)d_in[9];
    const float* bim   = (const float*)d_in[10];
    float* out = (float*)d_out;

    prep_w_kernel<<<dim3(16, 16, 3), dim3(32, 32)>>>(Wim, Wp, Wx);

    cudaFuncSetAttribute(embed_mma_kernel, cudaFuncAttributeMaxDynamicSharedMemorySize, EMB_SMEM);
    embed_mma_kernel<<<128, 256, EMB_SMEM>>>(x, bp, bx);

    cudaFuncSetAttribute(temporal_kernel, cudaFuncAttributeMaxDynamicSharedMemorySize, SMEM_BYTES);
    temporal_kernel<<<BB * 32, 512, SMEM_BYTES>>>(x, ts, amask, Wt, bt, bim, out);
}